// round 4
// baseline (speedup 1.0000x reference)
#include <cuda_runtime.h>
#include <cuda_bf16.h>

// ---------------------------------------------------------------------------
// RGBLambertianRendererWithVisibility — R4
//   Shared-memory staged loads: all global traffic is unit-stride LDG.128
//   (4 sectors/instruction); strided access happens in smem instead of L1tex.
// ---------------------------------------------------------------------------

#define MAX_RAYS 65536
__device__ float g_acc[MAX_RAYS * 4];
__device__ int   g_idx_is64;

__global__ void zero_acc_kernel(int n4) {
    int i = blockIdx.x * blockDim.x + threadIdx.x;
    if (i < n4) g_acc[i] = 0.0f;
    if (i == 0) g_idx_is64 = 0;
}

// Parallel dtype detection (int32 vs int64 ray_indices). Inspect the last
// 2048 of the first N int32 words (in-bounds for both layouts): sorted
// indices are nonzero there for int32; int64 interleaves zero high words.
__global__ void detect_idx_kernel(const int* __restrict__ words, int n_words_safe) {
    int end = n_words_safe;
    int start = end - 2048; if (start < 0) start = 0;
    int i = start + blockIdx.x * blockDim.x + threadIdx.x;
    int z = (i < end && words[i] == 0) ? 1 : 0;
    unsigned any = __ballot_sync(0xFFFFFFFFu, z);
    if ((threadIdx.x & 31) == 0 && any) atomicOr(&g_idx_is64, 1);
}

// --- main fused pass: 256 threads, 16 samples/block, smem staging ----------
#define SPB 16                      // samples per block
__global__ __launch_bounds__(256) void shade_kernel(
        const float* __restrict__ albedos,
        const float* __restrict__ normals,
        const float* __restrict__ ldir,
        const float* __restrict__ lcol,
        const float* __restrict__ vis,
        const float* __restrict__ weights,
        const void*  __restrict__ ray_idx,
        int N) {
    __shared__ float sm_dir[SPB * 192];   // 12 KB
    __shared__ float sm_col[SPB * 192];   // 12 KB
    __shared__ float sm_vis[SPB * 64];    //  4 KB

    int tid  = threadIdx.x;
    int base = blockIdx.x * SPB;          // first sample of this block
    int nloc = N - base; if (nloc > SPB) nloc = SPB;   // samples in this block

    // ---- stage: unit-stride float4 loads --------------------------------
    {
        const float4* gd = (const float4*)(ldir + (size_t)base * 192);
        const float4* gc = (const float4*)(lcol + (size_t)base * 192);
        const float4* gv = (const float4*)(vis  + (size_t)base * 64);
        float4* sd = (float4*)sm_dir;
        float4* sc = (float4*)sm_col;
        float4* sv = (float4*)sm_vis;
        int nf4  = nloc * 48;             // float4s of dir/col present
        int nf4v = nloc * 16;             // float4s of vis present
        #pragma unroll
        for (int k = 0; k < 3; ++k) {     // 768 float4 / 256 threads
            int i = tid + k * 256;
            if (i < nf4) {
                sd[i] = __ldcs(&gd[i]);
                sc[i] = __ldcs(&gc[i]);
            }
        }
        if (tid < nf4v) sv[tid] = __ldcs(&gv[tid]);
    }
    __syncthreads();

    // ---- compute: half-warp per sample -----------------------------------
    int warp = tid >> 5;                  // 0..7
    int lane = tid & 31;
    int half = lane >> 4;
    int sub  = lane & 15;
    int sl   = warp * 2 + half;           // local sample 0..15
    int s    = base + sl;
    if (s >= N) return;

    const float4* sd = (const float4*)(sm_dir + sl * 192);
    const float4* sc = (const float4*)(sm_col + sl * 192);
    const float4* sv = (const float4*)(sm_vis + sl * 64);

    float4 d0 = sd[sub * 3 + 0];
    float4 d1 = sd[sub * 3 + 1];
    float4 d2 = sd[sub * 3 + 2];
    float4 c0 = sc[sub * 3 + 0];
    float4 c1 = sc[sub * 3 + 1];
    float4 c2 = sc[sub * 3 + 2];
    float4 v  = sv[sub];

    float nx = normals[s * 3 + 0];
    float ny = normals[s * 3 + 1];
    float nz = normals[s * 3 + 2];

    float t0 = fmaf(nx, d0.x, fmaf(ny, d0.y, nz * d0.z));
    float t1 = fmaf(nx, d0.w, fmaf(ny, d1.x, nz * d1.y));
    float t2 = fmaf(nx, d1.z, fmaf(ny, d1.w, nz * d2.x));
    float t3 = fmaf(nx, d2.y, fmaf(ny, d2.z, nz * d2.w));

    int cnt = (t0 > 0.f) + (t1 > 0.f) + (t2 > 0.f) + (t3 > 0.f);

    t0 = fminf(fmaxf(t0, 0.f), 1.f) * v.x;
    t1 = fminf(fmaxf(t1, 0.f), 1.f) * v.y;
    t2 = fminf(fmaxf(t2, 0.f), 1.f) * v.z;
    t3 = fminf(fmaxf(t3, 0.f), 1.f) * v.w;

    float s0 = fmaf(t0, c0.x, fmaf(t1, c0.w, fmaf(t2, c1.z, t3 * c2.y)));
    float s1 = fmaf(t0, c0.y, fmaf(t1, c1.x, fmaf(t2, c1.w, t3 * c2.z)));
    float s2 = fmaf(t0, c0.z, fmaf(t1, c1.y, fmaf(t2, c2.x, t3 * c2.w)));

    #pragma unroll
    for (int off = 8; off; off >>= 1) {
        s0  += __shfl_xor_sync(0xFFFFFFFFu, s0,  off);
        s1  += __shfl_xor_sync(0xFFFFFFFFu, s1,  off);
        s2  += __shfl_xor_sync(0xFFFFFFFFu, s2,  off);
        cnt += __shfl_xor_sync(0xFFFFFFFFu, cnt, off);
    }

    if (sub == 0) {
        float c   = (cnt > 0) ? (float)cnt : 1.0f;
        float inv = 1.0f / c;
        float w   = weights[s];
        int r;
        if (g_idx_is64) r = (int)((const long long*)ray_idx)[s];
        else            r = ((const int*)ray_idx)[s];
        float a0 = albedos[s * 3 + 0];
        float a1 = albedos[s * 3 + 1];
        float a2 = albedos[s * 3 + 2];
        atomicAdd(&g_acc[r * 4 + 0], w * a0 * s0 * inv);
        atomicAdd(&g_acc[r * 4 + 1], w * a1 * s1 * inv);
        atomicAdd(&g_acc[r * 4 + 2], w * a2 * s2 * inv);
        atomicAdd(&g_acc[r * 4 + 3], w);
    }
}

__global__ void finalize_kernel(const float* __restrict__ bg,
                                float* __restrict__ out, int R) {
    int r = blockIdx.x * blockDim.x + threadIdx.x;
    if (r >= R) return;
    float aw = g_acc[r * 4 + 3];
    float one_m = 1.0f - aw;
    #pragma unroll
    for (int c = 0; c < 3; ++c) {
        float x = g_acc[r * 4 + c] + bg[r * 3 + c] * one_m;
        float safe = fmaxf(x, 1e-8f);
        float y = (x <= 0.0031308f) ? (12.92f * x)
                                    : (1.055f * powf(safe, 1.0f / 2.4f) - 0.055f);
        out[r * 3 + c] = y;
    }
}

// Fallback for L != 64
__global__ void shade_kernel_generic(
        const float* __restrict__ albedos,
        const float* __restrict__ normals,
        const float* __restrict__ ldir,
        const float* __restrict__ lcol,
        const float* __restrict__ vis,
        const float* __restrict__ weights,
        const void*  __restrict__ ray_idx,
        int N, int L) {
    int gwarp = (blockIdx.x * blockDim.x + threadIdx.x) >> 5;
    int lane  = threadIdx.x & 31;
    if (gwarp >= N) return;
    float nx = normals[gwarp * 3 + 0];
    float ny = normals[gwarp * 3 + 1];
    float nz = normals[gwarp * 3 + 2];
    const float* ldp = ldir + (size_t)gwarp * L * 3;
    const float* lcp = lcol + (size_t)gwarp * L * 3;
    const float* vp  = vis  + (size_t)gwarp * L;
    float s0 = 0.f, s1 = 0.f, s2 = 0.f;
    int cnt = 0;
    for (int j = lane; j < L; j += 32) {
        float dx = ldp[j * 3 + 0], dy = ldp[j * 3 + 1], dz = ldp[j * 3 + 2];
        float d  = fmaf(nx, dx, fmaf(ny, dy, nz * dz));
        cnt += (d > 0.f) ? 1 : 0;
        d = fminf(fmaxf(d, 0.f), 1.f);
        float dv = d * vp[j];
        s0 = fmaf(dv, lcp[j * 3 + 0], s0);
        s1 = fmaf(dv, lcp[j * 3 + 1], s1);
        s2 = fmaf(dv, lcp[j * 3 + 2], s2);
    }
    #pragma unroll
    for (int off = 16; off; off >>= 1) {
        s0  += __shfl_xor_sync(0xFFFFFFFFu, s0,  off);
        s1  += __shfl_xor_sync(0xFFFFFFFFu, s1,  off);
        s2  += __shfl_xor_sync(0xFFFFFFFFu, s2,  off);
        cnt += __shfl_xor_sync(0xFFFFFFFFu, cnt, off);
    }
    if (lane == 0) {
        float c   = (cnt > 0) ? (float)cnt : 1.0f;
        float inv = 1.0f / c;
        float w   = weights[gwarp];
        int r;
        if (g_idx_is64) r = (int)((const long long*)ray_idx)[gwarp];
        else            r = ((const int*)ray_idx)[gwarp];
        atomicAdd(&g_acc[r * 4 + 0], w * albedos[gwarp * 3 + 0] * s0 * inv);
        atomicAdd(&g_acc[r * 4 + 1], w * albedos[gwarp * 3 + 1] * s1 * inv);
        atomicAdd(&g_acc[r * 4 + 2], w * albedos[gwarp * 3 + 2] * s2 * inv);
        atomicAdd(&g_acc[r * 4 + 3], w);
    }
}

extern "C" void kernel_launch(void* const* d_in, const int* in_sizes, int n_in,
                              void* d_out, int out_size) {
    const float* albedos = (const float*)d_in[0];
    const float* normals = (const float*)d_in[1];
    const float* ldir    = (const float*)d_in[2];
    const float* lcol    = (const float*)d_in[3];
    const float* vis     = (const float*)d_in[4];
    const float* bg      = (const float*)d_in[5];
    const float* weights = (const float*)d_in[6];
    const void*  ray_idx = (const void*) d_in[7];
    float* out = (float*)d_out;

    int N = in_sizes[0] / 3;
    int L = (N > 0) ? in_sizes[2] / (N * 3) : 1;
    int R = out_size / 3;
    if (R > MAX_RAYS) R = MAX_RAYS;

    int n4 = R * 4;
    zero_acc_kernel<<<(n4 + 255) / 256, 256>>>(n4);

    detect_idx_kernel<<<2, 1024>>>((const int*)ray_idx, in_sizes[7]);

    if (L == 64) {
        int blocks = (N + SPB - 1) / SPB;
        shade_kernel<<<blocks, 256>>>(
            albedos, normals, ldir, lcol, vis, weights, ray_idx, N);
    } else {
        int blocks = (N + 7) / 8;
        shade_kernel_generic<<<blocks, 256>>>(
            albedos, normals, ldir, lcol, vis, weights, ray_idx, N, L);
    }

    finalize_kernel<<<(R + 255) / 256, 256>>>(bg, out, R);
}